// round 1
// baseline (speedup 1.0000x reference)
#include <cuda_runtime.h>

#define EPS 1e-7f

constexpr int T = 32;          // time steps (= u dim)
constexpr int S = 2048;        // seq len
constexpr int B = 512;         // batch
constexpr int SW = 16;         // s-values per block (= warps per block)
constexpr int BTILE = 16;      // b-values staged per iteration
constexpr int BGROUPS = 4;     // grid.y split over batch
constexpr int BPG = B / BGROUPS;   // 128 b per block
constexpr int NSB = S / SW;        // 128 s-blocks
constexpr int SMEM_FLOATS = 32*16*16 + 16*32*17;   // xs + op
constexpr int SMEM_BYTES = SMEM_FLOATS * 4;        // 67584 B

// scratch: partial[s_block][b][u]  (8.4 MB, written once per slot, no atomics)
__device__ float g_partial[(size_t)NSB * B * T];

__device__ __forceinline__ float tanh_approx(float x) {
    float y; asm("tanh.approx.f32 %0, %1;" : "=f"(y) : "f"(x)); return y;
}

__global__ __launch_bounds__(512, 2) void attn_main(
    const float* __restrict__ inp, const float* __restrict__ msk,
    const float* __restrict__ W,   const float* __restrict__ bias)
{
    extern __shared__ float sm[];
    float* xs = sm;                // [t=32][sl=16][bl=16]  masked inputs, 32 KB
    float* op = sm + 32*16*16;     // [bl=16][u=32][w pad 17] per-warp partials, 34.8 KB

    const int tid  = threadIdx.x;
    const int w    = tid >> 5;     // warp id = local s index
    const int lane = tid & 31;     // = u
    const int s0   = blockIdx.x * SW;
    const int bb   = blockIdx.y * BPG;
    const int s    = s0 + w;

    // W column for this (s, u=lane), register resident for the whole kernel
    float wreg[32];
    {
        const float* Wp = W + s * (T * T) + lane;
        #pragma unroll
        for (int t = 0; t < 32; t++) wreg[t] = Wp[t * 32];
    }
    const float breg = bias[s * 32 + lane];

    // staging thread mapping: lane-half -> sl (coalesced 64B rows), tt = t
    const int sl = tid & 15;
    const int tt = tid >> 4;       // 0..31
    const size_t gbase = (size_t)bb * (T * S) + (size_t)tt * S + s0 + sl;
    const float* ip0 = inp + gbase;
    const float* mp0 = msk + gbase;

    for (int bt = 0; bt < BPG; bt += BTILE) {
        // ---- stage x = inputs * mask for 16 b's, transposed to [t][sl][bl] ----
        #pragma unroll 4
        for (int bl = 0; bl < BTILE; bl++) {
            size_t off = (size_t)(bt + bl) * (T * S);
            xs[(tt * 16 + sl) * 16 + bl] = ip0[off] * mp0[off];
        }
        __syncthreads();

        // ---- compute: warp w handles s, 4 batch elements at a time ----
        #pragma unroll
        for (int q = 0; q < 4; q++) {
            float z0 = breg, z1 = breg, z2 = breg, z3 = breg;
            const float* xq = xs + w * 16 + q * 4;
            #pragma unroll
            for (int t = 0; t < 32; t++) {
                // broadcast LDS.128: x[t] for 4 b's (all lanes same address)
                float4 xb = *(const float4*)(xq + t * 256);
                z0 += xb.x * wreg[t];
                z1 += xb.y * wreg[t];
                z2 += xb.z * wreg[t];
                z3 += xb.w * wreg[t];
            }
            float e0 = __expf(tanh_approx(z0));
            float e1 = __expf(tanh_approx(z1));
            float e2 = __expf(tanh_approx(z2));
            float e3 = __expf(tanh_approx(z3));
            float r0 = e0, r1 = e1, r2 = e2, r3 = e3;
            #pragma unroll
            for (int o = 16; o; o >>= 1) {
                r0 += __shfl_xor_sync(~0u, r0, o);
                r1 += __shfl_xor_sync(~0u, r1, o);
                r2 += __shfl_xor_sync(~0u, r2, o);
                r3 += __shfl_xor_sync(~0u, r3, o);
            }
            // x at t = lane (= u) for the 4 b's
            float4 xu = *(const float4*)(xs + lane * 256 + w * 16 + q * 4);
            op[((q * 4 + 0) * 32 + lane) * 17 + w] = e0 / (r0 + EPS) * xu.x;
            op[((q * 4 + 1) * 32 + lane) * 17 + w] = e1 / (r1 + EPS) * xu.y;
            op[((q * 4 + 2) * 32 + lane) * 17 + w] = e2 / (r2 + EPS) * xu.z;
            op[((q * 4 + 3) * 32 + lane) * 17 + w] = e3 / (r3 + EPS) * xu.w;
        }
        __syncthreads();

        // ---- reduce the 16 warp contributions, write partial (no atomics) ----
        {
            const int bl = tid >> 5;   // 0..15
            const int u  = lane;
            const float* r = op + (bl * 32 + u) * 17;
            float sum = 0.f;
            #pragma unroll
            for (int k = 0; k < 16; k++) sum += r[k];
            g_partial[(size_t)blockIdx.x * (B * T) + (size_t)(bb + bt + bl) * 32 + u] = sum;
        }
        __syncthreads();
    }
}

__global__ void attn_reduce(float* __restrict__ out)
{
    const int i = blockIdx.x * blockDim.x + threadIdx.x;  // 0..16383 = (b,u)
    float s = 0.f;
    #pragma unroll 8
    for (int k = 0; k < NSB; k++)
        s += g_partial[(size_t)k * (B * T) + i];
    out[i] = s;
}

extern "C" void kernel_launch(void* const* d_in, const int* in_sizes, int n_in,
                              void* d_out, int out_size)
{
    const float* inp  = (const float*)d_in[0];
    const float* msk  = (const float*)d_in[1];
    const float* W    = (const float*)d_in[2];
    const float* bias = (const float*)d_in[3];
    float* out = (float*)d_out;

    // idempotent, not a graph node; needed because dynamic smem > 48KB
    cudaFuncSetAttribute(attn_main, cudaFuncAttributeMaxDynamicSharedMemorySize, SMEM_BYTES);

    dim3 grid(NSB, BGROUPS);
    attn_main<<<grid, 512, SMEM_BYTES>>>(inp, msk, W, bias);
    attn_reduce<<<(B * T) / 256, 256>>>(out);
}

// round 2
// speedup vs baseline: 1.2167x; 1.2167x over previous
#include <cuda_runtime.h>

#define EPS 1e-7f

constexpr int T = 32;           // time steps (= u dim)
constexpr int S = 2048;         // seq len
constexpr int B = 512;          // batch
constexpr int SW = 16;          // s-values per block (= warps per block)
constexpr int BTILE = 16;       // b-values staged per iteration
constexpr int BGROUPS = 4;
constexpr int BPG = B / BGROUPS;    // 128 b per block
constexpr int NSB = S / SW;         // 128 s-blocks
constexpr int BT = B * T;           // 16384

constexpr int XROW = 16 * 32 + 4;   // 516: per-s row (16 b x 32 t) + pad -> 2-way STS max
constexpr int XS_FLOATS = SW * XROW;        // 8256
constexpr int OP_FLOATS = 16 * 32 * 17;     // 8704
constexpr int SMEM_BYTES = (XS_FLOATS + OP_FLOATS) * 4;   // 67840 B

// deterministic scratch (no atomics): partial[s_block][b][u], then 8-deep stage
__device__ float g_partial[(size_t)NSB * BT];     // 8 MB
__device__ float g_partial2[8 * BT];              // 512 KB

__device__ __forceinline__ float tanh_approx(float x) {
    float y; asm("tanh.approx.f32 %0, %1;" : "=f"(y) : "f"(x)); return y;
}
__device__ __forceinline__ unsigned long long pack2(float lo, float hi) {
    unsigned long long r;
    asm("mov.b64 %0, {%1, %2};" : "=l"(r) : "f"(lo), "f"(hi));
    return r;
}
__device__ __forceinline__ void fma2(unsigned long long& d, unsigned long long a,
                                     unsigned long long b, unsigned long long c) {
    asm("fma.rn.f32x2 %0, %1, %2, %3;" : "=l"(d) : "l"(a), "l"(b), "l"(c));
}
__device__ __forceinline__ float unpack_sum(unsigned long long a, unsigned long long b) {
    float al, ah, bl, bh;
    asm("mov.b64 {%0, %1}, %2;" : "=f"(al), "=f"(ah) : "l"(a));
    asm("mov.b64 {%0, %1}, %2;" : "=f"(bl), "=f"(bh) : "l"(b));
    return (al + ah) + (bl + bh);
}

__global__ __launch_bounds__(512, 1) void attn_main(
    const float* __restrict__ inp, const float* __restrict__ msk,
    const float* __restrict__ W,   const float* __restrict__ bias)
{
    extern __shared__ float sm[];
    float* xs = sm;                 // [sl=16][bl=16][t=32] row-stride 516
    float* op = sm + XS_FLOATS;     // [bl=16][u=32][w=16 pad 17]

    const int tid  = threadIdx.x;
    const int w    = tid >> 5;      // warp id = local s index
    const int lane = tid & 31;      // = u
    const int s0   = blockIdx.x * SW;
    const int bb   = blockIdx.y * BPG;
    const int s    = s0 + w;

    // W for (s, u=lane), packed over t-pairs: w2[k] = {W[2k,u], W[2k+1,u]}
    unsigned long long w2[16];
    {
        const float* Wp = W + s * (T * T) + lane;
        #pragma unroll
        for (int k = 0; k < 16; k++)
            w2[k] = pack2(Wp[(2 * k) * 32], Wp[(2 * k + 1) * 32]);
    }
    const float breg = bias[s * 32 + lane];

    // staging mapping: half-warp -> 16 consecutive s (coalesced 64B), tt = t
    const int sl = tid & 15;
    const int tt = tid >> 4;        // 0..31
    const float* ip0 = inp + (size_t)bb * (T * S) + (size_t)tt * S + s0 + sl;
    const float* mp0 = msk + (size_t)bb * (T * S) + (size_t)tt * S + s0 + sl;

    // prefetch tile 0
    float vi[16], vm[16];
    #pragma unroll
    for (int bl = 0; bl < 16; bl++) {
        size_t off = (size_t)bl * (T * S);
        vi[bl] = ip0[off];
        vm[bl] = mp0[off];
    }

    for (int bt = 0; bt < BPG; bt += BTILE) {
        // ---- store staged x = inp*mask into xs[sl][bl][tt] (2-way STS max) ----
        {
            float* xrow = xs + sl * XROW + tt;
            #pragma unroll
            for (int bl = 0; bl < 16; bl++)
                xrow[bl * 32] = vi[bl] * vm[bl];
        }
        __syncthreads();

        // ---- prefetch next tile (latency hidden under compute) ----
        if (bt + BTILE < BPG) {
            const float* ipn = ip0 + (size_t)(bt + BTILE) * (T * S);
            const float* mpn = mp0 + (size_t)(bt + BTILE) * (T * S);
            #pragma unroll
            for (int bl = 0; bl < 16; bl++) {
                size_t off = (size_t)bl * (T * S);
                vi[bl] = ipn[off];
                vm[bl] = mpn[off];
            }
        }

        // ---- compute: warp w owns s, 4 batch elements per q ----
        #pragma unroll
        for (int q = 0; q < 4; q++) {
            const float* xb = xs + w * XROW + (q * 4) * 32;
            const ulonglong2* xp0 = (const ulonglong2*)(xb);
            const ulonglong2* xp1 = (const ulonglong2*)(xb + 32);
            const ulonglong2* xp2 = (const ulonglong2*)(xb + 64);
            const ulonglong2* xp3 = (const ulonglong2*)(xb + 96);
            unsigned long long A0 = 0, A1 = 0, B0 = 0, B1 = 0;
            unsigned long long C0 = 0, C1 = 0, D0 = 0, D1 = 0;
            #pragma unroll
            for (int h = 0; h < 8; h++) {
                ulonglong2 v0 = xp0[h];   // LDS.128 broadcast: {x[4h..4h+3]}
                ulonglong2 v1 = xp1[h];
                ulonglong2 v2 = xp2[h];
                ulonglong2 v3 = xp3[h];
                fma2(A0, v0.x, w2[2 * h], A0); fma2(A1, v0.y, w2[2 * h + 1], A1);
                fma2(B0, v1.x, w2[2 * h], B0); fma2(B1, v1.y, w2[2 * h + 1], B1);
                fma2(C0, v2.x, w2[2 * h], C0); fma2(C1, v2.y, w2[2 * h + 1], C1);
                fma2(D0, v3.x, w2[2 * h], D0); fma2(D1, v3.y, w2[2 * h + 1], D1);
            }
            float z0 = unpack_sum(A0, A1) + breg;
            float z1 = unpack_sum(B0, B1) + breg;
            float z2 = unpack_sum(C0, C1) + breg;
            float z3 = unpack_sum(D0, D1) + breg;

            float e0 = __expf(tanh_approx(z0));
            float e1 = __expf(tanh_approx(z1));
            float e2 = __expf(tanh_approx(z2));
            float e3 = __expf(tanh_approx(z3));

            float r0 = e0, r1 = e1, r2 = e2, r3 = e3;
            #pragma unroll
            for (int o = 16; o; o >>= 1) {
                r0 += __shfl_xor_sync(~0u, r0, o);
                r1 += __shfl_xor_sync(~0u, r1, o);
                r2 += __shfl_xor_sync(~0u, r2, o);
                r3 += __shfl_xor_sync(~0u, r3, o);
            }

            // x at t = lane (= u): conflict-free scalar LDS
            float xu0 = xb[lane];
            float xu1 = xb[32 + lane];
            float xu2 = xb[64 + lane];
            float xu3 = xb[96 + lane];

            op[((q * 4 + 0) * 32 + lane) * 17 + w] = __fdividef(e0, r0 + EPS) * xu0;
            op[((q * 4 + 1) * 32 + lane) * 17 + w] = __fdividef(e1, r1 + EPS) * xu1;
            op[((q * 4 + 2) * 32 + lane) * 17 + w] = __fdividef(e2, r2 + EPS) * xu2;
            op[((q * 4 + 3) * 32 + lane) * 17 + w] = __fdividef(e3, r3 + EPS) * xu3;
        }
        __syncthreads();

        // ---- reduce 16 warp contributions -> partial slice (deterministic) ----
        {
            const int blr = tid >> 5;   // 0..15
            const float* r = op + (blr * 32 + lane) * 17;
            float sum = 0.f;
            #pragma unroll
            for (int k = 0; k < 16; k++) sum += r[k];
            g_partial[(size_t)blockIdx.x * BT + (size_t)(bb + bt + blr) * T + lane] = sum;
        }
        // next iteration's first __syncthreads() orders op reuse; no barrier needed here
    }
}

// stage A: 131072 threads, each sums 16 of the 128 s-block slices
__global__ void attn_reduceA()
{
    const int i = blockIdx.x * 256 + threadIdx.x;   // 0..16383
    const int j = blockIdx.y;                        // 0..7
    const float* p = g_partial + (size_t)j * 16 * BT + i;
    float s = 0.f;
    #pragma unroll
    for (int k = 0; k < 16; k++) s += p[(size_t)k * BT];
    g_partial2[j * BT + i] = s;
}

// stage B: final 8-way sum
__global__ void attn_reduceB(float* __restrict__ out)
{
    const int i = blockIdx.x * 256 + threadIdx.x;
    float s = 0.f;
    #pragma unroll
    for (int j = 0; j < 8; j++) s += g_partial2[j * BT + i];
    out[i] = s;
}

extern "C" void kernel_launch(void* const* d_in, const int* in_sizes, int n_in,
                              void* d_out, int out_size)
{
    const float* inp  = (const float*)d_in[0];
    const float* msk  = (const float*)d_in[1];
    const float* W    = (const float*)d_in[2];
    const float* bias = (const float*)d_in[3];
    float* out = (float*)d_out;

    cudaFuncSetAttribute(attn_main, cudaFuncAttributeMaxDynamicSharedMemorySize, SMEM_BYTES);

    dim3 grid(NSB, BGROUPS);
    attn_main<<<grid, 512, SMEM_BYTES>>>(inp, msk, W, bias);
    attn_reduceA<<<dim3(BT / 256, 8), 256>>>();
    attn_reduceB<<<BT / 256, 256>>>(out);
}